// round 1
// baseline (speedup 1.0000x reference)
#include <cuda_runtime.h>
#include <math.h>

#define NN  50000
#define TT  8
#define EE  800000
#define FIN 9
#define HH  64
#define GG  256   // 4*H

// ---------------- scratch (__device__ globals; no allocation allowed) ------
__device__ int   g_deg[NN];
__device__ int   g_fill[NN];
__device__ int   g_ptr[NN + 1];
__device__ int   g_csr[EE];
__device__ float g_dinv[NN];
__device__ float g_hs[NN * HH];          // dinv-scaled features of current layer
__device__ float g_act[NN * HH];         // layer-1 activation
__device__ float g_seq[TT * NN * HH];    // GCN encoder outputs per timestep
__device__ float g_gx[TT * NN * GG];     // precomputed seq @ w_ih^T + bias  (409.6 MB)
__device__ float g_gates[NN * GG];       // per-step full gates
__device__ float g_h[NN * HH];
__device__ float g_c[NN * HH];
__device__ float g_wihT[HH * GG];        // w_ih transposed to [k][j]
__device__ float g_whhT[HH * GG];        // w_hh transposed to [k][j]

// ---------------- packed fp32x2 FMA (sm_100a) ------------------------------
__device__ __forceinline__ void ffma2(float2& d, const float2& a, const float2& b) {
    asm("fma.rn.f32x2 %0, %1, %2, %0;"
        : "+l"(reinterpret_cast<unsigned long long&>(d))
        : "l"(reinterpret_cast<const unsigned long long&>(a)),
          "l"(reinterpret_cast<const unsigned long long&>(b)));
}

__device__ __forceinline__ float sigf(float x) { return 1.f / (1.f + __expf(-x)); }

// ---------------- init: transpose LSTM weights, zero h/c -------------------
__global__ void k_init(const float* __restrict__ w_ih, const float* __restrict__ w_hh) {
    int idx = blockIdx.x * blockDim.x + threadIdx.x;
    if (idx < HH * GG) {
        int k = idx >> 8, j = idx & 255;
        g_wihT[idx] = w_ih[j * HH + k];
        g_whhT[idx] = w_hh[j * HH + k];
    }
    for (int i = idx; i < NN * HH; i += gridDim.x * blockDim.x) {
        g_h[i] = 0.f;
        g_c[i] = 0.f;
    }
}

__global__ void k_zero_deg() {
    int n = blockIdx.x * blockDim.x + threadIdx.x;
    if (n < NN) { g_deg[n] = 0; g_fill[n] = 0; }
}

__global__ void k_hist(const int* __restrict__ dst) {
    int e = blockIdx.x * blockDim.x + threadIdx.x;
    if (e < EE) atomicAdd(&g_deg[dst[e]], 1);
}

// exclusive prefix-sum over deg -> csr_ptr ; dinv = rsqrt(deg+1)
__global__ void k_scan() {
    __shared__ int part[1024];
    int tid = threadIdx.x;
    const int chunk = (NN + 1023) / 1024;   // 49
    int beg = tid * chunk;
    int end = min(beg + chunk, NN);
    int s = 0;
    for (int i = beg; i < end; i++) s += g_deg[i];
    part[tid] = s;
    __syncthreads();
    for (int off = 1; off < 1024; off <<= 1) {
        int v = part[tid];
        int add = (tid >= off) ? part[tid - off] : 0;
        __syncthreads();
        part[tid] = v + add;
        __syncthreads();
    }
    int excl = (tid == 0) ? 0 : part[tid - 1];
    for (int i = beg; i < end; i++) {
        int d = g_deg[i];
        g_ptr[i] = excl;
        excl += d;
        g_dinv[i] = rsqrtf((float)(d + 1));
    }
    if (tid == 1023) g_ptr[NN] = excl;   // == EE
}

__global__ void k_fill(const int* __restrict__ src, const int* __restrict__ dst) {
    int e = blockIdx.x * blockDim.x + threadIdx.x;
    if (e < EE) {
        int d = dst[e];
        int pos = g_ptr[d] + atomicAdd(&g_fill[d], 1);
        g_csr[pos] = src[e];
    }
}

// ---------------- layer-1 GEMM: hs = (x @ W1) * dinv  (K=9) ----------------
__global__ void k_gemm1(const float* __restrict__ x, const float* __restrict__ W1) {
    __shared__ float sW[FIN * HH];
    int tid = threadIdx.x;
    for (int i = tid; i < FIN * HH; i += blockDim.x) sW[i] = W1[i];
    __syncthreads();
    int n = blockIdx.x * blockDim.x + tid;
    if (n >= NN) return;
    float xv[FIN];
#pragma unroll
    for (int k = 0; k < FIN; k++) xv[k] = x[n * FIN + k];
    float dv = g_dinv[n];
#pragma unroll
    for (int c = 0; c < HH; c += 4) {
        float4 o = make_float4(0.f, 0.f, 0.f, 0.f);
#pragma unroll
        for (int k = 0; k < FIN; k++) {
            float xk = xv[k];
            o.x = fmaf(xk, sW[k * HH + c + 0], o.x);
            o.y = fmaf(xk, sW[k * HH + c + 1], o.y);
            o.z = fmaf(xk, sW[k * HH + c + 2], o.z);
            o.w = fmaf(xk, sW[k * HH + c + 3], o.w);
        }
        o.x *= dv; o.y *= dv; o.z *= dv; o.w *= dv;
        *reinterpret_cast<float4*>(g_hs + n * HH + c) = o;
    }
}

// ---------------- aggregation: out = relu(dinv*(sum_in hs + hs_self) + b) --
__global__ void k_agg(const float* __restrict__ hs, float* __restrict__ out,
                      const float* __restrict__ b) {
    int gw = (blockIdx.x * blockDim.x + threadIdx.x) >> 5;
    int lane = threadIdx.x & 31;
    if (gw >= NN) return;
    const float2* h2 = reinterpret_cast<const float2*>(hs);
    float2 acc = h2[gw * 32 + lane];          // self-loop term (already dinv-scaled)
    int e = g_ptr[gw], end = g_ptr[gw + 1];
    for (; e + 1 < end; e += 2) {
        int s0 = g_csr[e], s1 = g_csr[e + 1];
        float2 v0 = h2[s0 * 32 + lane];
        float2 v1 = h2[s1 * 32 + lane];
        acc.x += v0.x + v1.x;
        acc.y += v0.y + v1.y;
    }
    if (e < end) {
        int s0 = g_csr[e];
        float2 v0 = h2[s0 * 32 + lane];
        acc.x += v0.x;
        acc.y += v0.y;
    }
    float dv = g_dinv[gw];
    float2 bb = reinterpret_cast<const float2*>(b)[lane];
    float2 o;
    o.x = fmaxf(fmaf(acc.x, dv, bb.x), 0.f);
    o.y = fmaxf(fmaf(acc.y, dv, bb.y), 0.f);
    reinterpret_cast<float2*>(out)[gw * 32 + lane] = o;
}

// ---------------- generic K=64 GEMM, f32x2 packed --------------------------
// C[M,OUT] = A[M,64] @ Wt[64,OUT]  (+ epilogue per MODE)
//   MODE 0: C = acc * dinv[row]                 (GCN layer 2 -> hs)
//   MODE 1: C = acc + aux0[col] + aux1[col]     (input gates + bias)
//   MODE 2: C = acc + aux0[row*OUT + col]       (recurrent gates += gx)
template <int OUT, int MODE>
__global__ __launch_bounds__(512) void k_gemm(
    const float* __restrict__ A, const float* __restrict__ Wt,
    float* __restrict__ C, const float* __restrict__ aux0,
    const float* __restrict__ aux1, int M)
{
    constexpr int TC = OUT / 16;                 // cols per warp (16 warps)
    __shared__ float sAT[64 * 65];               // A tile transposed, pad->conflict-free
    int tid  = threadIdx.x;
    int lane = tid & 31, warp = tid >> 5;
    int r0 = blockIdx.x * 64;

#pragma unroll
    for (int it = 0; it < 2; it++) {
        int idx4 = tid + it * 512;               // 0..1023
        int r = idx4 >> 4;                       // 0..63
        int k4 = idx4 & 15;
        float4 v = make_float4(0.f, 0.f, 0.f, 0.f);
        int row = r0 + r;
        if (row < M) v = *reinterpret_cast<const float4*>(A + (size_t)row * 64 + k4 * 4);
        sAT[(k4 * 4 + 0) * 65 + r] = v.x;
        sAT[(k4 * 4 + 1) * 65 + r] = v.y;
        sAT[(k4 * 4 + 2) * 65 + r] = v.z;
        sAT[(k4 * 4 + 3) * 65 + r] = v.w;
    }
    __syncthreads();

    int c0 = warp * TC;
    float2 acc[TC];
#pragma unroll
    for (int c = 0; c < TC; c++) acc[c] = make_float2(0.f, 0.f);

#pragma unroll 4
    for (int k = 0; k < 64; k++) {
        float2 av = make_float2(sAT[k * 65 + lane], sAT[k * 65 + lane + 32]);
        const float* wr = Wt + k * OUT + c0;     // uniform per warp -> L1 broadcast
#pragma unroll
        for (int c = 0; c < TC; c += 4) {
            float4 wv = *reinterpret_cast<const float4*>(wr + c);
            ffma2(acc[c + 0], av, make_float2(wv.x, wv.x));
            ffma2(acc[c + 1], av, make_float2(wv.y, wv.y));
            ffma2(acc[c + 2], av, make_float2(wv.z, wv.z));
            ffma2(acc[c + 3], av, make_float2(wv.w, wv.w));
        }
    }

#pragma unroll
    for (int i = 0; i < 2; i++) {
        int row = r0 + lane + 32 * i;
        if (row >= M) continue;
        float dv = (MODE == 0) ? g_dinv[row] : 1.f;
#pragma unroll
        for (int c = 0; c < TC; c += 4) {
            float4 o;
            o.x = (i == 0) ? acc[c + 0].x : acc[c + 0].y;
            o.y = (i == 0) ? acc[c + 1].x : acc[c + 1].y;
            o.z = (i == 0) ? acc[c + 2].x : acc[c + 2].y;
            o.w = (i == 0) ? acc[c + 3].x : acc[c + 3].y;
            if (MODE == 0) { o.x *= dv; o.y *= dv; o.z *= dv; o.w *= dv; }
            if (MODE == 1) {
                o.x += aux0[c0 + c + 0] + aux1[c0 + c + 0];
                o.y += aux0[c0 + c + 1] + aux1[c0 + c + 1];
                o.z += aux0[c0 + c + 2] + aux1[c0 + c + 2];
                o.w += aux0[c0 + c + 3] + aux1[c0 + c + 3];
            }
            if (MODE == 2) {
                float4 g = *reinterpret_cast<const float4*>(aux0 + (size_t)row * OUT + c0 + c);
                o.x += g.x; o.y += g.y; o.z += g.z; o.w += g.w;
            }
            *reinterpret_cast<float4*>(C + (size_t)row * OUT + c0 + c) = o;
        }
    }
}

// ---------------- LSTM elementwise update ----------------------------------
__global__ void k_lstm_ew() {
    int idx = blockIdx.x * blockDim.x + threadIdx.x;
    if (idx >= NN * HH) return;
    int n = idx >> 6, c = idx & 63;
    const float* gr = g_gates + n * GG;
    float gi = gr[c], gf = gr[64 + c], gg = gr[128 + c], go = gr[192 + c];
    float cc = sigf(gf) * g_c[idx] + sigf(gi) * tanhf(gg);
    g_c[idx] = cc;
    g_h[idx] = sigf(go) * tanhf(cc);
}

// ---------------- head: logits[n] = h[n] . head_w + head_b -----------------
__global__ void k_head(float* __restrict__ out, const float* __restrict__ hw,
                       const float* __restrict__ hb) {
    int gw = (blockIdx.x * blockDim.x + threadIdx.x) >> 5;
    int lane = threadIdx.x & 31;
    if (gw >= NN) return;
    float2 h = reinterpret_cast<const float2*>(g_h)[gw * 32 + lane];
    float2 w = reinterpret_cast<const float2*>(hw)[lane];
    float s = h.x * w.x + h.y * w.y;
#pragma unroll
    for (int off = 16; off; off >>= 1) s += __shfl_xor_sync(0xffffffffu, s, off);
    if (lane == 0) out[gw] = s + hb[0];
}

// ---------------- host launch ----------------------------------------------
extern "C" void kernel_launch(void* const* d_in, const int* in_sizes, int n_in,
                              void* d_out, int out_size) {
    const float* xs  = (const float*)d_in[0];
    const int*   ei  = (const int*)  d_in[1];
    const float* W1  = (const float*)d_in[2];
    const float* b1  = (const float*)d_in[3];
    const float* W2  = (const float*)d_in[4];
    const float* b2  = (const float*)d_in[5];
    const float* wih = (const float*)d_in[6];
    const float* whh = (const float*)d_in[7];
    const float* bih = (const float*)d_in[8];
    const float* bhh = (const float*)d_in[9];
    const float* hw  = (const float*)d_in[10];
    const float* hb  = (const float*)d_in[11];
    float* out = (float*)d_out;

    float *p_hs, *p_act, *p_seq, *p_gx, *p_gates, *p_h, *p_wihT, *p_whhT;
    cudaGetSymbolAddress((void**)&p_hs,    g_hs);
    cudaGetSymbolAddress((void**)&p_act,   g_act);
    cudaGetSymbolAddress((void**)&p_seq,   g_seq);
    cudaGetSymbolAddress((void**)&p_gx,    g_gx);
    cudaGetSymbolAddress((void**)&p_gates, g_gates);
    cudaGetSymbolAddress((void**)&p_h,     g_h);
    cudaGetSymbolAddress((void**)&p_wihT,  g_wihT);
    cudaGetSymbolAddress((void**)&p_whhT,  g_whhT);

    k_init<<<(NN * HH + 255) / 256, 256>>>(wih, whh);

    for (int t = 0; t < TT; t++) {
        const int* src = ei + (size_t)t * 2 * EE;
        const int* dst = src + EE;
        const float* xt = xs + (size_t)t * NN * FIN;

        k_zero_deg<<<(NN + 255) / 256, 256>>>();
        k_hist<<<(EE + 255) / 256, 256>>>(dst);
        k_scan<<<1, 1024>>>();
        k_fill<<<(EE + 255) / 256, 256>>>(src, dst);

        // layer 1
        k_gemm1<<<(NN + 127) / 128, 128>>>(xt, W1);
        k_agg<<<(NN * 32 + 255) / 256, 256>>>(p_hs, p_act, b1);

        // layer 2
        k_gemm<HH, 0><<<(NN + 63) / 64, 512>>>(p_act, W2, p_hs, nullptr, nullptr, NN);
        k_agg<<<(NN * 32 + 255) / 256, 256>>>(p_hs, p_seq + (size_t)t * NN * HH, b2);
    }

    // input-gate GEMM for all timesteps at once: [T*N,64] @ [64,256] + bias
    k_gemm<GG, 1><<<(TT * NN + 63) / 64, 512>>>(p_seq, p_wihT, p_gx, bih, bhh, TT * NN);

    // recurrent LSTM steps
    for (int t = 0; t < TT; t++) {
        k_gemm<GG, 2><<<(NN + 63) / 64, 512>>>(p_h, p_whhT, p_gates,
                                               p_gx + (size_t)t * NN * GG, nullptr, NN);
        k_lstm_ew<<<(NN * HH + 255) / 256, 256>>>();
    }

    k_head<<<(NN * 32 + 255) / 256, 256>>>(out, hw, hb);
}

// round 2
// speedup vs baseline: 1.5488x; 1.5488x over previous
#include <cuda_runtime.h>
#include <math.h>

#define NN  50000
#define TT  8
#define EE  800000
#define FIN 9
#define HH  64
#define GG  256   // 4*H

// ---------------- scratch (__device__ globals; no allocation allowed) ------
__device__ int   g_deg [TT * NN];
__device__ int   g_fill[TT * NN];
__device__ int   g_ptr [TT * (NN + 1)];
__device__ int   g_csr [TT * EE];          // stores pre-offset src: t*NN + s
__device__ float g_dinv[TT * NN];
__device__ float g_hs  [TT * NN * HH];     // dinv-scaled features (102.4 MB)
__device__ float g_act [TT * NN * HH];     // layer-1 act, then final seq (102.4 MB)
__device__ float g_h   [NN * HH];
__device__ float g_c   [NN * HH];
__device__ float g_wcomb[128 * GG];        // [k][j]: k<64 -> w_ih^T, k>=64 -> w_hh^T
__device__ float g_bias [GG];              // b_ih + b_hh

// ---------------- packed fp32x2 FMA (sm_100a full-rate fp32) ---------------
__device__ __forceinline__ void ffma2(float2& d, const float2& a, const float2& b) {
    asm("fma.rn.f32x2 %0, %1, %2, %0;"
        : "+l"(reinterpret_cast<unsigned long long&>(d))
        : "l"(reinterpret_cast<const unsigned long long&>(a)),
          "l"(reinterpret_cast<const unsigned long long&>(b)));
}

__device__ __forceinline__ float sigf(float x) {
    return __fdividef(1.f, 1.f + __expf(-x));
}
__device__ __forceinline__ float tanhf_fast(float x) {
    float a = fabsf(x);
    float e = __expf(-2.f * a);
    float t = __fdividef(1.f - e, 1.f + e);
    return copysignf(t, x);
}

// ---------------- init: combined weights, bias, zero deg/fill/h/c ----------
__global__ void k_init(const float* __restrict__ w_ih, const float* __restrict__ w_hh,
                       const float* __restrict__ b_ih, const float* __restrict__ b_hh) {
    int stride = gridDim.x * blockDim.x;
    int idx0 = blockIdx.x * blockDim.x + threadIdx.x;
    for (int idx = idx0; idx < 128 * GG; idx += stride) {
        int k = idx >> 8, j = idx & 255;
        g_wcomb[idx] = (k < 64) ? w_ih[j * HH + k] : w_hh[j * HH + (k - 64)];
    }
    if (idx0 < GG) g_bias[idx0] = b_ih[idx0] + b_hh[idx0];
    for (int i = idx0; i < NN * HH; i += stride) { g_h[i] = 0.f; g_c[i] = 0.f; }
    for (int i = idx0; i < TT * NN; i += stride) { g_deg[i] = 0; g_fill[i] = 0; }
}

// ---------------- CSR build for ALL timesteps at once ----------------------
__global__ void k_hist_all(const int* __restrict__ ei) {
    int idx = blockIdx.x * blockDim.x + threadIdx.x;
    if (idx >= TT * EE) return;
    int t = idx / EE, e = idx - t * EE;
    int d = ei[(size_t)t * 2 * EE + EE + e];
    atomicAdd(&g_deg[t * NN + d], 1);
}

// 8 blocks, one per timestep; coalesced strip-mined block scan w/ prefetch
__global__ __launch_bounds__(1024) void k_scan_all() {
    int t = blockIdx.x;
    const int* deg = g_deg + t * NN;
    int*   ptr  = g_ptr  + t * (NN + 1);
    float* dinv = g_dinv + t * NN;
    __shared__ int s_ws[32];
    int tid = threadIdx.x, lane = tid & 31, wid = tid >> 5;
    const int iters = (NN + 1023) / 1024;   // 49
    int running = 0;
    int i = tid;
    int v = (i < NN) ? deg[i] : 0;
    for (int it = 0; it < iters; it++) {
        int inext = (it + 1) * 1024 + tid;
        int vnext = (it + 1 < iters && inext < NN) ? deg[inext] : 0;
        // warp inclusive scan
        int x = v;
#pragma unroll
        for (int off = 1; off < 32; off <<= 1) {
            int y = __shfl_up_sync(0xffffffffu, x, off);
            if (lane >= off) x += y;
        }
        if (lane == 31) s_ws[wid] = x;
        __syncthreads();
        if (wid == 0) {
            int w = s_ws[lane];
#pragma unroll
            for (int off = 1; off < 32; off <<= 1) {
                int y = __shfl_up_sync(0xffffffffu, w, off);
                if (lane >= off) w += y;
            }
            s_ws[lane] = w;
        }
        __syncthreads();
        int base  = (wid > 0) ? s_ws[wid - 1] : 0;
        int total = s_ws[31];
        if (i < NN) {
            ptr[i]  = running + base + (x - v);
            dinv[i] = rsqrtf((float)(v + 1));
        }
        __syncthreads();
        running += total;
        i = inext; v = vnext;
    }
    if (tid == 0) ptr[NN] = running;
}

__global__ void k_fill_all(const int* __restrict__ ei) {
    int idx = blockIdx.x * blockDim.x + threadIdx.x;
    if (idx >= TT * EE) return;
    int t = idx / EE, e = idx - t * EE;
    int s = ei[(size_t)t * 2 * EE + e];
    int d = ei[(size_t)t * 2 * EE + EE + e];
    int pos = g_ptr[t * (NN + 1) + d] + atomicAdd(&g_fill[t * NN + d], 1);
    g_csr[(size_t)t * EE + pos] = t * NN + s;   // pre-offset source row
}

// ---------------- layer-1 GEMM (K=9), batched over T -----------------------
__global__ void k_gemm1(const float* __restrict__ x, const float* __restrict__ W1) {
    __shared__ float sW[FIN * HH];
    int tid = threadIdx.x;
    for (int i = tid; i < FIN * HH; i += blockDim.x) sW[i] = W1[i];
    __syncthreads();
    int n = blockIdx.x * blockDim.x + tid;    // global row in [0, T*N)
    if (n >= TT * NN) return;
    float xv[FIN];
#pragma unroll
    for (int k = 0; k < FIN; k++) xv[k] = x[(size_t)n * FIN + k];
    float dv = g_dinv[n];
#pragma unroll
    for (int c = 0; c < HH; c += 4) {
        float4 o = make_float4(0.f, 0.f, 0.f, 0.f);
#pragma unroll
        for (int k = 0; k < FIN; k++) {
            float xk = xv[k];
            o.x = fmaf(xk, sW[k * HH + c + 0], o.x);
            o.y = fmaf(xk, sW[k * HH + c + 1], o.y);
            o.z = fmaf(xk, sW[k * HH + c + 2], o.z);
            o.w = fmaf(xk, sW[k * HH + c + 3], o.w);
        }
        o.x *= dv; o.y *= dv; o.z *= dv; o.w *= dv;
        *reinterpret_cast<float4*>(g_hs + (size_t)n * HH + c) = o;
    }
}

// ------- aggregation, batched over T: out = relu(dinv*(sum hs + self) + b) -
__global__ void k_agg(const float* __restrict__ hs, float* __restrict__ out,
                      const float* __restrict__ b) {
    int gw = (blockIdx.x * blockDim.x + threadIdx.x) >> 5;  // t*NN + n
    int lane = threadIdx.x & 31;
    if (gw >= TT * NN) return;
    int t = gw / NN, n = gw - t * NN;
    const int* pbase = g_ptr + t * (NN + 1) + n;
    const int* csr   = g_csr + (size_t)t * EE;
    const float2* h2 = reinterpret_cast<const float2*>(hs);
    float2 acc = h2[(size_t)gw * 32 + lane];   // self-loop (already dinv-scaled)
    int e = pbase[0], end = pbase[1];
    for (; e + 1 < end; e += 2) {
        int s0 = csr[e], s1 = csr[e + 1];
        float2 v0 = h2[(size_t)s0 * 32 + lane];
        float2 v1 = h2[(size_t)s1 * 32 + lane];
        acc.x += v0.x + v1.x;
        acc.y += v0.y + v1.y;
    }
    if (e < end) {
        int s0 = csr[e];
        float2 v0 = h2[(size_t)s0 * 32 + lane];
        acc.x += v0.x; acc.y += v0.y;
    }
    float dv = g_dinv[gw];
    float2 bb = reinterpret_cast<const float2*>(b)[lane];
    float2 o;
    o.x = fmaxf(fmaf(acc.x, dv, bb.x), 0.f);
    o.y = fmaxf(fmaf(acc.y, dv, bb.y), 0.f);
    reinterpret_cast<float2*>(out)[(size_t)gw * 32 + lane] = o;
}

// ---------------- K=64 GEMM, f32x2, C = (A @ Wt) * dinv[row] ---------------
__global__ __launch_bounds__(512) void k_gemm64(
    const float* __restrict__ A, const float* __restrict__ Wt,
    float* __restrict__ C, int M)
{
    constexpr int TC = 4;                    // 64 cols / 16 warps
    __shared__ float sAT[64 * 65];
    int tid = threadIdx.x, lane = tid & 31, warp = tid >> 5;
    int r0 = blockIdx.x * 64;

#pragma unroll
    for (int it = 0; it < 2; it++) {
        int idx4 = tid + it * 512;
        int r = idx4 >> 4, k4 = idx4 & 15;
        float4 v = make_float4(0.f, 0.f, 0.f, 0.f);
        int row = r0 + r;
        if (row < M) v = *reinterpret_cast<const float4*>(A + (size_t)row * 64 + k4 * 4);
        sAT[(k4 * 4 + 0) * 65 + r] = v.x;
        sAT[(k4 * 4 + 1) * 65 + r] = v.y;
        sAT[(k4 * 4 + 2) * 65 + r] = v.z;
        sAT[(k4 * 4 + 3) * 65 + r] = v.w;
    }
    __syncthreads();

    int c0 = warp * TC;
    float2 acc[TC];
#pragma unroll
    for (int c = 0; c < TC; c++) acc[c] = make_float2(0.f, 0.f);

#pragma unroll 4
    for (int k = 0; k < 64; k++) {
        float2 av = make_float2(sAT[k * 65 + lane], sAT[k * 65 + lane + 32]);
        float4 wv = *reinterpret_cast<const float4*>(Wt + k * 64 + c0);
        ffma2(acc[0], av, make_float2(wv.x, wv.x));
        ffma2(acc[1], av, make_float2(wv.y, wv.y));
        ffma2(acc[2], av, make_float2(wv.z, wv.z));
        ffma2(acc[3], av, make_float2(wv.w, wv.w));
    }

#pragma unroll
    for (int i = 0; i < 2; i++) {
        int row = r0 + lane + 32 * i;
        if (row >= M) continue;
        float dv = g_dinv[row];
        float4 o;
        o.x = ((i == 0) ? acc[0].x : acc[0].y) * dv;
        o.y = ((i == 0) ? acc[1].x : acc[1].y) * dv;
        o.z = ((i == 0) ? acc[2].x : acc[2].y) * dv;
        o.w = ((i == 0) ? acc[3].x : acc[3].y) * dv;
        *reinterpret_cast<float4*>(C + (size_t)row * 64 + c0) = o;
    }
}

// ------- fused LSTM step: gates = [seq_t | h] @ wcomb + bias; update c,h ---
// 16 warps; warp w owns cols w*4..w*4+3 of EACH gate quarter.
__global__ __launch_bounds__(512, 2) void k_lstm_step(const float* __restrict__ seqt) {
    __shared__ float sAT[128 * 65];          // [k][row], padded
    int tid = threadIdx.x, lane = tid & 31, warp = tid >> 5;
    int r0 = blockIdx.x * 64;

#pragma unroll
    for (int it = 0; it < 4; it++) {
        int fi = tid + it * 512;             // 0..2047 float4s
        int r = fi >> 5, k4 = fi & 31;
        int row = r0 + r;
        float4 v = make_float4(0.f, 0.f, 0.f, 0.f);
        if (row < NN) {
            const float* srcp = (k4 < 16)
                ? (seqt + (size_t)row * 64 + k4 * 4)
                : (g_h  + (size_t)row * 64 + (k4 - 16) * 4);
            v = *reinterpret_cast<const float4*>(srcp);
        }
        int kk = k4 * 4;
        sAT[(kk + 0) * 65 + r] = v.x;
        sAT[(kk + 1) * 65 + r] = v.y;
        sAT[(kk + 2) * 65 + r] = v.z;
        sAT[(kk + 3) * 65 + r] = v.w;
    }
    __syncthreads();

    int c0 = warp * 4;
    float2 acc[16];                          // [gate q][j]
#pragma unroll
    for (int c = 0; c < 16; c++) acc[c] = make_float2(0.f, 0.f);

#pragma unroll 2
    for (int k = 0; k < 128; k++) {
        float2 av = make_float2(sAT[k * 65 + lane], sAT[k * 65 + lane + 32]);
        const float* wr = g_wcomb + k * GG;
#pragma unroll
        for (int q = 0; q < 4; q++) {
            float4 wv = *reinterpret_cast<const float4*>(wr + q * 64 + c0);
            ffma2(acc[q * 4 + 0], av, make_float2(wv.x, wv.x));
            ffma2(acc[q * 4 + 1], av, make_float2(wv.y, wv.y));
            ffma2(acc[q * 4 + 2], av, make_float2(wv.z, wv.z));
            ffma2(acc[q * 4 + 3], av, make_float2(wv.w, wv.w));
        }
    }

    float bi[4], bf[4], bg[4], bo[4];
#pragma unroll
    for (int j = 0; j < 4; j++) {
        bi[j] = g_bias[0 * 64 + c0 + j];
        bf[j] = g_bias[1 * 64 + c0 + j];
        bg[j] = g_bias[2 * 64 + c0 + j];
        bo[j] = g_bias[3 * 64 + c0 + j];
    }

#pragma unroll
    for (int i = 0; i < 2; i++) {
        int row = r0 + lane + 32 * i;
        if (row >= NN) continue;
        float4 cold = *reinterpret_cast<const float4*>(g_c + (size_t)row * 64 + c0);
        float co[4] = {cold.x, cold.y, cold.z, cold.w};
        float cn[4], hn[4];
#pragma unroll
        for (int j = 0; j < 4; j++) {
            float gi = (i == 0) ? acc[0 * 4 + j].x : acc[0 * 4 + j].y;
            float gf = (i == 0) ? acc[1 * 4 + j].x : acc[1 * 4 + j].y;
            float gg = (i == 0) ? acc[2 * 4 + j].x : acc[2 * 4 + j].y;
            float go = (i == 0) ? acc[3 * 4 + j].x : acc[3 * 4 + j].y;
            float cc = sigf(gf + bf[j]) * co[j] + sigf(gi + bi[j]) * tanhf_fast(gg + bg[j]);
            cn[j] = cc;
            hn[j] = sigf(go + bo[j]) * tanhf_fast(cc);
        }
        *reinterpret_cast<float4*>(g_c + (size_t)row * 64 + c0) =
            make_float4(cn[0], cn[1], cn[2], cn[3]);
        *reinterpret_cast<float4*>(g_h + (size_t)row * 64 + c0) =
            make_float4(hn[0], hn[1], hn[2], hn[3]);
    }
}

// ---------------- head: logits[n] = h[n] . head_w + head_b -----------------
__global__ void k_head(float* __restrict__ out, const float* __restrict__ hw,
                       const float* __restrict__ hb) {
    int gw = (blockIdx.x * blockDim.x + threadIdx.x) >> 5;
    int lane = threadIdx.x & 31;
    if (gw >= NN) return;
    float2 h = reinterpret_cast<const float2*>(g_h)[(size_t)gw * 32 + lane];
    float2 w = reinterpret_cast<const float2*>(hw)[lane];
    float s = h.x * w.x + h.y * w.y;
#pragma unroll
    for (int off = 16; off; off >>= 1) s += __shfl_xor_sync(0xffffffffu, s, off);
    if (lane == 0) out[gw] = s + hb[0];
}

// ---------------- host launch ----------------------------------------------
extern "C" void kernel_launch(void* const* d_in, const int* in_sizes, int n_in,
                              void* d_out, int out_size) {
    const float* xs  = (const float*)d_in[0];
    const int*   ei  = (const int*)  d_in[1];
    const float* W1  = (const float*)d_in[2];
    const float* b1  = (const float*)d_in[3];
    const float* W2  = (const float*)d_in[4];
    const float* b2  = (const float*)d_in[5];
    const float* wih = (const float*)d_in[6];
    const float* whh = (const float*)d_in[7];
    const float* bih = (const float*)d_in[8];
    const float* bhh = (const float*)d_in[9];
    const float* hw  = (const float*)d_in[10];
    const float* hb  = (const float*)d_in[11];
    float* out = (float*)d_out;

    float *p_hs, *p_act;
    cudaGetSymbolAddress((void**)&p_hs,  g_hs);
    cudaGetSymbolAddress((void**)&p_act, g_act);

    k_init<<<2048, 256>>>(wih, whh, bih, bhh);

    // CSR for all timesteps
    k_hist_all<<<(TT * EE + 255) / 256, 256>>>(ei);
    k_scan_all<<<TT, 1024>>>();
    k_fill_all<<<(TT * EE + 255) / 256, 256>>>(ei);

    // GCN encoder, batched over all timesteps
    k_gemm1<<<(TT * NN + 127) / 128, 128>>>(xs, W1);
    k_agg<<<((size_t)TT * NN * 32 + 511) / 512, 512>>>(p_hs, p_act, b1);
    k_gemm64<<<(TT * NN + 63) / 64, 512>>>(p_act, W2, p_hs, TT * NN);
    k_agg<<<((size_t)TT * NN * 32 + 511) / 512, 512>>>(p_hs, p_act, b2);  // p_act = seq

    // fused LSTM over T
    for (int t = 0; t < TT; t++)
        k_lstm_step<<<(NN + 63) / 64, 512>>>(p_act + (size_t)t * NN * HH);

    k_head<<<((size_t)NN * 32 + 255) / 256, 256>>>(out, hw, hb);
}

// round 4
// speedup vs baseline: 2.1906x; 1.4144x over previous
#include <cuda_runtime.h>
#include <math.h>
#include <stdint.h>

#define NN  50000
#define TT  8
#define EE  800000
#define FIN 9
#define HH  64
#define GG  256   // 4*H
#define TILE_M 128
#define NBLK ((NN + TILE_M - 1) / TILE_M)   // 391

// ---------------- scratch (__device__ globals) -----------------------------
__device__ int   g_deg [TT * NN];
__device__ int   g_fill[TT * NN];
__device__ int   g_ptr [TT * (NN + 1)];
__device__ int   g_csr [TT * EE];          // pre-offset src: t*NN + s
__device__ float g_dinv[TT * NN];
__device__ float g_hs  [TT * NN * HH];
__device__ float g_act [TT * NN * HH];     // layer-1 act, then seq

// ---------------- packed fp32x2 FMA ----------------------------------------
__device__ __forceinline__ void ffma2(float2& d, const float2& a, const float2& b) {
    asm("fma.rn.f32x2 %0, %1, %2, %0;"
        : "+l"(reinterpret_cast<unsigned long long&>(d))
        : "l"(reinterpret_cast<const unsigned long long&>(a)),
          "l"(reinterpret_cast<const unsigned long long&>(b)));
}
__device__ __forceinline__ float sigf(float x) {
    return __fdividef(1.f, 1.f + __expf(-x));
}
__device__ __forceinline__ float tanhf_fast(float x) {
    float a = fabsf(x);
    float e = __expf(-2.f * a);
    float t = __fdividef(1.f - e, 1.f + e);
    return copysignf(t, x);
}

// ---------------- tf32 mma helpers (sm_80+, works on plain sm_100) ---------
__device__ __forceinline__ void split_tf32(float x, uint32_t& hi, uint32_t& lo) {
    uint32_t h;
    asm("cvt.rna.tf32.f32 %0, %1;" : "=r"(h) : "f"(x));
    float l = x - __uint_as_float(h);
    uint32_t lw;
    asm("cvt.rna.tf32.f32 %0, %1;" : "=r"(lw) : "f"(l));
    hi = h; lo = lw;
}
__device__ __forceinline__ void mma_tf32(float* d, const uint32_t* a,
                                         uint32_t b0, uint32_t b1) {
    asm volatile(
        "mma.sync.aligned.m16n8k8.row.col.f32.tf32.tf32.f32 "
        "{%0,%1,%2,%3}, {%4,%5,%6,%7}, {%8,%9}, {%0,%1,%2,%3};"
        : "+f"(d[0]), "+f"(d[1]), "+f"(d[2]), "+f"(d[3])
        : "r"(a[0]), "r"(a[1]), "r"(a[2]), "r"(a[3]), "r"(b0), "r"(b1));
}

// ---------------- init: zero deg/fill --------------------------------------
__global__ void k_init() {
    int i0 = blockIdx.x * blockDim.x + threadIdx.x;
    for (int i = i0; i < TT * NN; i += gridDim.x * blockDim.x) {
        g_deg[i] = 0; g_fill[i] = 0;
    }
}

// ---------------- CSR build ------------------------------------------------
__global__ void k_hist_all(const int* __restrict__ ei) {
    int idx = blockIdx.x * blockDim.x + threadIdx.x;
    if (idx >= TT * EE) return;
    int t = idx / EE, e = idx - t * EE;
    int d = ei[(size_t)t * 2 * EE + EE + e];
    atomicAdd(&g_deg[t * NN + d], 1);
}

__global__ __launch_bounds__(1024) void k_scan_all() {
    int t = blockIdx.x;
    const int* deg = g_deg + t * NN;
    int*   ptr  = g_ptr  + t * (NN + 1);
    float* dinv = g_dinv + t * NN;
    __shared__ int s_ws[32];
    int tid = threadIdx.x, lane = tid & 31, wid = tid >> 5;
    const int iters = (NN + 1023) / 1024;
    int running = 0;
    int i = tid;
    int v = (i < NN) ? deg[i] : 0;
    for (int it = 0; it < iters; it++) {
        int inext = (it + 1) * 1024 + tid;
        int vnext = (it + 1 < iters && inext < NN) ? deg[inext] : 0;
        int x = v;
#pragma unroll
        for (int off = 1; off < 32; off <<= 1) {
            int y = __shfl_up_sync(0xffffffffu, x, off);
            if (lane >= off) x += y;
        }
        if (lane == 31) s_ws[wid] = x;
        __syncthreads();
        if (wid == 0) {
            int w = s_ws[lane];
#pragma unroll
            for (int off = 1; off < 32; off <<= 1) {
                int y = __shfl_up_sync(0xffffffffu, w, off);
                if (lane >= off) w += y;
            }
            s_ws[lane] = w;
        }
        __syncthreads();
        int base  = (wid > 0) ? s_ws[wid - 1] : 0;
        int total = s_ws[31];
        if (i < NN) {
            ptr[i]  = running + base + (x - v);
            dinv[i] = rsqrtf((float)(v + 1));
        }
        __syncthreads();
        running += total;
        i = inext; v = vnext;
    }
    if (tid == 0) ptr[NN] = running;
}

__global__ void k_fill_all(const int* __restrict__ ei) {
    int idx = blockIdx.x * blockDim.x + threadIdx.x;
    if (idx >= TT * EE) return;
    int t = idx / EE, e = idx - t * EE;
    int s = ei[(size_t)t * 2 * EE + e];
    int d = ei[(size_t)t * 2 * EE + EE + e];
    int pos = g_ptr[t * (NN + 1) + d] + atomicAdd(&g_fill[t * NN + d], 1);
    g_csr[(size_t)t * EE + pos] = t * NN + s;
}

// ---------------- layer-1 GEMM (K=9) ---------------------------------------
__global__ void k_gemm1(const float* __restrict__ x, const float* __restrict__ W1) {
    __shared__ float sW[FIN * HH];
    int tid = threadIdx.x;
    for (int i = tid; i < FIN * HH; i += blockDim.x) sW[i] = W1[i];
    __syncthreads();
    int n = blockIdx.x * blockDim.x + tid;
    if (n >= TT * NN) return;
    float xv[FIN];
#pragma unroll
    for (int k = 0; k < FIN; k++) xv[k] = x[(size_t)n * FIN + k];
    float dv = g_dinv[n];
#pragma unroll
    for (int c = 0; c < HH; c += 4) {
        float4 o = make_float4(0.f, 0.f, 0.f, 0.f);
#pragma unroll
        for (int k = 0; k < FIN; k++) {
            float xk = xv[k];
            o.x = fmaf(xk, sW[k * HH + c + 0], o.x);
            o.y = fmaf(xk, sW[k * HH + c + 1], o.y);
            o.z = fmaf(xk, sW[k * HH + c + 2], o.z);
            o.w = fmaf(xk, sW[k * HH + c + 3], o.w);
        }
        o.x *= dv; o.y *= dv; o.z *= dv; o.w *= dv;
        *reinterpret_cast<float4*>(g_hs + (size_t)n * HH + c) = o;
    }
}

// ---------------- aggregation ----------------------------------------------
__global__ void k_agg(const float* __restrict__ hs, float* __restrict__ out,
                      const float* __restrict__ b) {
    int gw = (blockIdx.x * blockDim.x + threadIdx.x) >> 5;
    int lane = threadIdx.x & 31;
    if (gw >= TT * NN) return;
    int t = gw / NN, n = gw - t * NN;
    const int* pbase = g_ptr + t * (NN + 1) + n;
    const int* csr   = g_csr + (size_t)t * EE;
    const float2* h2 = reinterpret_cast<const float2*>(hs);
    float2 acc = h2[(size_t)gw * 32 + lane];
    int e = pbase[0], end = pbase[1];
    for (; e + 1 < end; e += 2) {
        int s0 = csr[e], s1 = csr[e + 1];
        float2 v0 = h2[(size_t)s0 * 32 + lane];
        float2 v1 = h2[(size_t)s1 * 32 + lane];
        acc.x += v0.x + v1.x;
        acc.y += v0.y + v1.y;
    }
    if (e < end) {
        int s0 = csr[e];
        float2 v0 = h2[(size_t)s0 * 32 + lane];
        acc.x += v0.x; acc.y += v0.y;
    }
    float dv = g_dinv[gw];
    float2 bb = reinterpret_cast<const float2*>(b)[lane];
    float2 o;
    o.x = fmaxf(fmaf(acc.x, dv, bb.x), 0.f);
    o.y = fmaxf(fmaf(acc.y, dv, bb.y), 0.f);
    reinterpret_cast<float2*>(out)[(size_t)gw * 32 + lane] = o;
}

// ---------------- K=64 GEMM, f32x2, C = (A @ Wt) * dinv[row] ---------------
__global__ __launch_bounds__(512) void k_gemm64(
    const float* __restrict__ A, const float* __restrict__ Wt,
    float* __restrict__ C, int M)
{
    __shared__ float sAT[64 * 65];
    int tid = threadIdx.x, lane = tid & 31, warp = tid >> 5;
    int r0 = blockIdx.x * 64;
#pragma unroll
    for (int it = 0; it < 2; it++) {
        int idx4 = tid + it * 512;
        int r = idx4 >> 4, k4 = idx4 & 15;
        float4 v = make_float4(0.f, 0.f, 0.f, 0.f);
        int row = r0 + r;
        if (row < M) v = *reinterpret_cast<const float4*>(A + (size_t)row * 64 + k4 * 4);
        sAT[(k4 * 4 + 0) * 65 + r] = v.x;
        sAT[(k4 * 4 + 1) * 65 + r] = v.y;
        sAT[(k4 * 4 + 2) * 65 + r] = v.z;
        sAT[(k4 * 4 + 3) * 65 + r] = v.w;
    }
    __syncthreads();
    int c0 = warp * 4;
    float2 acc[4];
#pragma unroll
    for (int c = 0; c < 4; c++) acc[c] = make_float2(0.f, 0.f);
#pragma unroll 4
    for (int k = 0; k < 64; k++) {
        float2 av = make_float2(sAT[k * 65 + lane], sAT[k * 65 + lane + 32]);
        float4 wv = *reinterpret_cast<const float4*>(Wt + k * 64 + c0);
        ffma2(acc[0], av, make_float2(wv.x, wv.x));
        ffma2(acc[1], av, make_float2(wv.y, wv.y));
        ffma2(acc[2], av, make_float2(wv.z, wv.z));
        ffma2(acc[3], av, make_float2(wv.w, wv.w));
    }
#pragma unroll
    for (int i = 0; i < 2; i++) {
        int row = r0 + lane + 32 * i;
        if (row >= M) continue;
        float dv = g_dinv[row];
        float4 o;
        o.x = ((i == 0) ? acc[0].x : acc[0].y) * dv;
        o.y = ((i == 0) ? acc[1].x : acc[1].y) * dv;
        o.z = ((i == 0) ? acc[2].x : acc[2].y) * dv;
        o.w = ((i == 0) ? acc[3].x : acc[3].y) * dv;
        *reinterpret_cast<float4*>(C + (size_t)row * 64 + c0) = o;
    }
}

// ============== fused LSTM over all T + head, tf32x3 mma.sync ==============
// SMEM float offsets
#define OFF_X    0        // 128 x 68
#define OFF_H    8704     // 128 x 68
#define OFF_B    17408    // 128 x 264 (permuted gate columns)
#define OFF_BIAS 51200    // 256
#define OFF_LOG  51456    // 128
#define SMEM_F   51584
#define SMEM_BYTES (SMEM_F * 4)

__global__ __launch_bounds__(512, 1) void k_lstm_mma(
    const float* __restrict__ seq,
    const float* __restrict__ w_ih, const float* __restrict__ w_hh,
    const float* __restrict__ b_ih, const float* __restrict__ b_hh,
    const float* __restrict__ head_w, const float* __restrict__ head_b,
    float* __restrict__ out)
{
    extern __shared__ float sm[];
    float* sX = sm + OFF_X;
    float* sH = sm + OFF_H;
    float* sB = sm + OFF_B;
    float* sBias = sm + OFF_BIAS;
    float* sLog = sm + OFF_LOG;

    int tid = threadIdx.x, lane = tid & 31, w = tid >> 5;
    int grp = lane >> 2, tig = lane & 3;
    int wm = w >> 3, wn = w & 7;          // wm: row half (64 rows), wn: 8 hidden j
    int row0 = blockIdx.x * TILE_M;
    int j0 = (wn << 3) + tig, j1 = j0 + 4;

    // ---- load B (permuted gate columns), pad stride 264 -------------------
    // physical col p = wnp*32 + q*8 + e; gate = (q&1)*2 + (e&1);
    // j = wnp*8 + (q>>1)*4 + (e>>1); logical row L = gate*64 + j
    for (int i = tid; i < 256 * 32; i += 512) {
        int p = i >> 5, kq = i & 31, k0 = kq << 2;
        int wnp = p >> 5, rem = p & 31, q = rem >> 3, e = rem & 7;
        int gate = ((q & 1) << 1) | (e & 1);
        int j = (wnp << 3) + ((q >> 1) << 2) + (e >> 1);
        int L = (gate << 6) + j;
        float4 v = (k0 < 64)
            ? *reinterpret_cast<const float4*>(w_ih + (size_t)L * 64 + k0)
            : *reinterpret_cast<const float4*>(w_hh + (size_t)L * 64 + (k0 - 64));
        sB[(k0 + 0) * 264 + p] = v.x;
        sB[(k0 + 1) * 264 + p] = v.y;
        sB[(k0 + 2) * 264 + p] = v.z;
        sB[(k0 + 3) * 264 + p] = v.w;
    }
    // zero h, logits; load bias
    for (int i = tid; i < 128 * 68; i += 512) sH[i] = 0.f;
    if (tid < 256) sBias[tid] = b_ih[tid] + b_hh[tid];
    if (tid < 128) sLog[tid] = 0.f;
    // load x(0)
#pragma unroll
    for (int u = 0; u < 4; u++) {
        int ii = tid + u * 512;
        int r = ii >> 4, k4 = (ii & 15) << 2;
        int row = row0 + r;
        float4 v = make_float4(0.f, 0.f, 0.f, 0.f);
        if (row < NN) v = *reinterpret_cast<const float4*>(seq + (size_t)row * HH + k4);
        *reinterpret_cast<float4*>(sX + r * 68 + k4) = v;
    }
    float hw0 = head_w[j0], hw1 = head_w[j1];
    float creg[4][2][2];
#pragma unroll
    for (int a = 0; a < 4; a++)
#pragma unroll
        for (int b = 0; b < 2; b++) { creg[a][b][0] = 0.f; creg[a][b][1] = 0.f; }
    __syncthreads();

    for (int t = 0; t < TT; t++) {
        float acc[4][4][4];
#pragma unroll
        for (int a = 0; a < 4; a++)
#pragma unroll
            for (int q = 0; q < 4; q++)
#pragma unroll
                for (int cix = 0; cix < 4; cix++) acc[a][q][cix] = 0.f;

#pragma unroll 1
        for (int ks = 0; ks < 16; ks++) {
            const float* src = (ks < 8) ? sX : sH;
            int cb = (ks & 7) << 3;
            int kb = ks << 3;
            // B fragments (hi/lo), once per ks
            uint32_t Bh[4][2], Bl[4][2];
#pragma unroll
            for (int q = 0; q < 4; q++) {
                int p = (wn << 5) + (q << 3) + grp;
                split_tf32(sB[(kb + tig) * 264 + p],     Bh[q][0], Bl[q][0]);
                split_tf32(sB[(kb + tig + 4) * 264 + p], Bh[q][1], Bl[q][1]);
            }
#pragma unroll
            for (int half = 0; half < 2; half++) {
                uint32_t Ah[2][4], Al[2][4];
#pragma unroll
                for (int m2 = 0; m2 < 2; m2++) {
                    int rb = (wm << 6) + ((half * 2 + m2) << 4) + grp;
                    split_tf32(src[rb * 68 + cb + tig],           Ah[m2][0], Al[m2][0]);
                    split_tf32(src[(rb + 8) * 68 + cb + tig],     Ah[m2][1], Al[m2][1]);
                    split_tf32(src[rb * 68 + cb + tig + 4],       Ah[m2][2], Al[m2][2]);
                    split_tf32(src[(rb + 8) * 68 + cb + tig + 4], Ah[m2][3], Al[m2][3]);
                }
#pragma unroll
                for (int q = 0; q < 4; q++)
#pragma unroll
                    for (int m2 = 0; m2 < 2; m2++) {
                        float* d = acc[half * 2 + m2][q];
                        mma_tf32(d, Ah[m2], Bh[q][0], Bh[q][1]);
                        mma_tf32(d, Ah[m2], Bl[q][0], Bl[q][1]);
                        mma_tf32(d, Al[m2], Bh[q][0], Bh[q][1]);
                    }
            }
        }
        __syncthreads();   // all A reads done before h/x rewrite

        // ---- epilogue: gates -> c,h ---------------------------------------
        float bi0 = sBias[j0], bf0 = sBias[64 + j0], bg0 = sBias[128 + j0], bo0 = sBias[192 + j0];
        float bi1 = sBias[j1], bf1 = sBias[64 + j1], bg1 = sBias[128 + j1], bo1 = sBias[192 + j1];
#pragma unroll
        for (int mi = 0; mi < 4; mi++)
#pragma unroll
            for (int rh = 0; rh < 2; rh++) {
                int r = (wm << 6) + (mi << 4) + grp + (rh << 3);
                int ci = rh << 1;
                float gi0 = acc[mi][0][ci] + bi0, gf0 = acc[mi][0][ci + 1] + bf0;
                float gg0 = acc[mi][1][ci] + bg0, go0 = acc[mi][1][ci + 1] + bo0;
                float gi1 = acc[mi][2][ci] + bi1, gf1 = acc[mi][2][ci + 1] + bf1;
                float gg1 = acc[mi][3][ci] + bg1, go1 = acc[mi][3][ci + 1] + bo1;
                float c0 = creg[mi][rh][0], c1 = creg[mi][rh][1];
                c0 = sigf(gf0) * c0 + sigf(gi0) * tanhf_fast(gg0);
                c1 = sigf(gf1) * c1 + sigf(gi1) * tanhf_fast(gg1);
                creg[mi][rh][0] = c0; creg[mi][rh][1] = c1;
                float h0 = sigf(go0) * tanhf_fast(c0);
                float h1 = sigf(go1) * tanhf_fast(c1);
                if (t < TT - 1) {
                    sH[r * 68 + j0] = h0;
                    sH[r * 68 + j1] = h1;
                } else {
                    float v = h0 * hw0 + h1 * hw1;
                    v += __shfl_xor_sync(0xffffffffu, v, 1);
                    v += __shfl_xor_sync(0xffffffffu, v, 2);
                    if (tig == 0) atomicAdd(&sLog[r], v);
                }
            }

        // ---- load x(t+1) ---------------------------------------------------
        if (t < TT - 1) {
            const float* st = seq + (size_t)(t + 1) * NN * HH;
#pragma unroll
            for (int u = 0; u < 4; u++) {
                int ii = tid + u * 512;
                int r = ii >> 4, k4 = (ii & 15) << 2;
                int row = row0 + r;
                float4 v = make_float4(0.f, 0.f, 0.f, 0.f);
                if (row < NN) v = *reinterpret_cast<const float4*>(st + (size_t)row * HH + k4);
                *reinterpret_cast<float4*>(sX + r * 68 + k4) = v;
            }
        }
        __syncthreads();
    }

    if (tid < 128) {
        int row = row0 + tid;
        if (row < NN) out[row] = sLog[tid] + head_b[0];
    }
}

// ---------------- host launch ----------------------------------------------
extern "C" void kernel_launch(void* const* d_in, const int* in_sizes, int n_in,
                              void* d_out, int out_size) {
    const float* xs  = (const float*)d_in[0];
    const int*   ei  = (const int*)  d_in[1];
    const float* W1  = (const float*)d_in[2];
    const float* b1  = (const float*)d_in[3];
    const float* W2  = (const float*)d_in[4];
    const float* b2  = (const float*)d_in[5];
    const float* wih = (const float*)d_in[6];
    const float* whh = (const float*)d_in[7];
    const float* bih = (const float*)d_in[8];
    const float* bhh = (const float*)d_in[9];
    const float* hw  = (const float*)d_in[10];
    const float* hb  = (const float*)d_in[11];
    float* out = (float*)d_out;

    float *p_hs, *p_act;
    cudaGetSymbolAddress((void**)&p_hs,  g_hs);
    cudaGetSymbolAddress((void**)&p_act, g_act);

    cudaFuncSetAttribute(k_lstm_mma,
                         cudaFuncAttributeMaxDynamicSharedMemorySize, SMEM_BYTES);

    k_init<<<(TT * NN + 255) / 256, 256>>>();
    k_hist_all<<<(TT * EE + 255) / 256, 256>>>(ei);
    k_scan_all<<<TT, 1024>>>();
    k_fill_all<<<(TT * EE + 255) / 256, 256>>>(ei);

    k_gemm1<<<(TT * NN + 127) / 128, 128>>>(xs, W1);
    k_agg<<<((size_t)TT * NN * 32 + 511) / 512, 512>>>(p_hs, p_act, b1);
    k_gemm64<<<(TT * NN + 63) / 64, 512>>>(p_act, W2, p_hs, TT * NN);
    k_agg<<<((size_t)TT * NN * 32 + 511) / 512, 512>>>(p_hs, p_act, b2);

    k_lstm_mma<<<NBLK, 512, SMEM_BYTES>>>(p_act, wih, whh, bih, bhh, hw, hb, out);
}

// round 5
// speedup vs baseline: 3.1089x; 1.4192x over previous
#include <cuda_runtime.h>
#include <cuda_bf16.h>
#include <math.h>
#include <stdint.h>

#define NN  50000
#define TT  8
#define EE  800000
#define FIN 9
#define HH  64
#define GG  256   // 4*H
#define TILE_M 128
#define NBLK ((NN + TILE_M - 1) / TILE_M)   // 391

// ---------------- scratch (__device__ globals) -----------------------------
__device__ int   g_deg [TT * NN];
__device__ int   g_fill[TT * NN];
__device__ int   g_ptr [TT * (NN + 1)];
__device__ int   g_csr [TT * EE];          // pre-offset src: t*NN + s
__device__ float g_dinv[TT * NN];
__device__ float g_hs  [TT * NN * HH];
__device__ float g_act [TT * NN * HH];     // layer-1 act, then seq

// ---------------- math helpers ---------------------------------------------
__device__ __forceinline__ float sigf(float x) {
    return __fdividef(1.f, 1.f + __expf(-x));
}
__device__ __forceinline__ float tanhf_fast(float x) {
    float a = fabsf(x);
    float e = __expf(-2.f * a);
    float t = __fdividef(1.f - e, 1.f + e);
    return copysignf(t, x);
}

// ---------------- bf16 split helpers ---------------------------------------
// pack: low 16 bits = bf16(e0) (even k), high = bf16(e1) (odd k)
__device__ __forceinline__ uint32_t packbf(float e0, float e1) {
    uint32_t r;
    asm("cvt.rn.bf16x2.f32 %0, %1, %2;" : "=r"(r) : "f"(e1), "f"(e0));
    return r;
}
__device__ __forceinline__ float2 unpackbf(uint32_t u) {
    __nv_bfloat162 b = *reinterpret_cast<__nv_bfloat162*>(&u);
    return make_float2(__bfloat162float(b.x), __bfloat162float(b.y));
}
__device__ __forceinline__ void split2(float e0, float e1, uint32_t& hi, uint32_t& lo) {
    hi = packbf(e0, e1);
    float2 hf = unpackbf(hi);
    lo = packbf(e0 - hf.x, e1 - hf.y);
}
__device__ __forceinline__ void mma_bf16(float* d, const uint32_t* a,
                                         uint32_t b0, uint32_t b1) {
    asm volatile(
        "mma.sync.aligned.m16n8k16.row.col.f32.bf16.bf16.f32 "
        "{%0,%1,%2,%3}, {%4,%5,%6,%7}, {%8,%9}, {%0,%1,%2,%3};"
        : "+f"(d[0]), "+f"(d[1]), "+f"(d[2]), "+f"(d[3])
        : "r"(a[0]), "r"(a[1]), "r"(a[2]), "r"(a[3]), "r"(b0), "r"(b1));
}

// ---------------- init: zero deg/fill --------------------------------------
__global__ void k_init() {
    int i0 = blockIdx.x * blockDim.x + threadIdx.x;
    for (int i = i0; i < TT * NN; i += gridDim.x * blockDim.x) {
        g_deg[i] = 0; g_fill[i] = 0;
    }
}

// ---------------- CSR build ------------------------------------------------
__global__ void k_hist_all(const int* __restrict__ ei) {
    int idx = blockIdx.x * blockDim.x + threadIdx.x;
    if (idx >= TT * EE) return;
    int t = idx / EE, e = idx - t * EE;
    int d = ei[(size_t)t * 2 * EE + EE + e];
    atomicAdd(&g_deg[t * NN + d], 1);
}

__global__ __launch_bounds__(1024) void k_scan_all() {
    int t = blockIdx.x;
    const int* deg = g_deg + t * NN;
    int*   ptr  = g_ptr  + t * (NN + 1);
    float* dinv = g_dinv + t * NN;
    __shared__ int s_ws[32];
    int tid = threadIdx.x, lane = tid & 31, wid = tid >> 5;
    const int iters = (NN + 1023) / 1024;
    int running = 0;
    int i = tid;
    int v = (i < NN) ? deg[i] : 0;
    for (int it = 0; it < iters; it++) {
        int inext = (it + 1) * 1024 + tid;
        int vnext = (it + 1 < iters && inext < NN) ? deg[inext] : 0;
        int x = v;
#pragma unroll
        for (int off = 1; off < 32; off <<= 1) {
            int y = __shfl_up_sync(0xffffffffu, x, off);
            if (lane >= off) x += y;
        }
        if (lane == 31) s_ws[wid] = x;
        __syncthreads();
        if (wid == 0) {
            int w = s_ws[lane];
#pragma unroll
            for (int off = 1; off < 32; off <<= 1) {
                int y = __shfl_up_sync(0xffffffffu, w, off);
                if (lane >= off) w += y;
            }
            s_ws[lane] = w;
        }
        __syncthreads();
        int base  = (wid > 0) ? s_ws[wid - 1] : 0;
        int total = s_ws[31];
        if (i < NN) {
            ptr[i]  = running + base + (x - v);
            dinv[i] = rsqrtf((float)(v + 1));
        }
        __syncthreads();
        running += total;
        i = inext; v = vnext;
    }
    if (tid == 0) ptr[NN] = running;
}

__global__ void k_fill_all(const int* __restrict__ ei) {
    int idx = blockIdx.x * blockDim.x + threadIdx.x;
    if (idx >= TT * EE) return;
    int t = idx / EE, e = idx - t * EE;
    int s = ei[(size_t)t * 2 * EE + e];
    int d = ei[(size_t)t * 2 * EE + EE + e];
    int pos = g_ptr[t * (NN + 1) + d] + atomicAdd(&g_fill[t * NN + d], 1);
    g_csr[(size_t)t * EE + pos] = t * NN + s;
}

// ---------------- layer-1 GEMM (K=9) ---------------------------------------
__global__ void k_gemm1(const float* __restrict__ x, const float* __restrict__ W1) {
    __shared__ float sW[FIN * HH];
    int tid = threadIdx.x;
    for (int i = tid; i < FIN * HH; i += blockDim.x) sW[i] = W1[i];
    __syncthreads();
    int n = blockIdx.x * blockDim.x + tid;
    if (n >= TT * NN) return;
    float xv[FIN];
#pragma unroll
    for (int k = 0; k < FIN; k++) xv[k] = x[(size_t)n * FIN + k];
    float dv = g_dinv[n];
#pragma unroll
    for (int c = 0; c < HH; c += 4) {
        float4 o = make_float4(0.f, 0.f, 0.f, 0.f);
#pragma unroll
        for (int k = 0; k < FIN; k++) {
            float xk = xv[k];
            o.x = fmaf(xk, sW[k * HH + c + 0], o.x);
            o.y = fmaf(xk, sW[k * HH + c + 1], o.y);
            o.z = fmaf(xk, sW[k * HH + c + 2], o.z);
            o.w = fmaf(xk, sW[k * HH + c + 3], o.w);
        }
        o.x *= dv; o.y *= dv; o.z *= dv; o.w *= dv;
        *reinterpret_cast<float4*>(g_hs + (size_t)n * HH + c) = o;
    }
}

// ---------------- aggregation (unroll 4) -----------------------------------
__global__ void k_agg(const float* __restrict__ hs, float* __restrict__ out,
                      const float* __restrict__ b) {
    int gw = (blockIdx.x * blockDim.x + threadIdx.x) >> 5;
    int lane = threadIdx.x & 31;
    if (gw >= TT * NN) return;
    int t = gw / NN, n = gw - t * NN;
    const int* pbase = g_ptr + t * (NN + 1) + n;
    const int* csr   = g_csr + (size_t)t * EE;
    const float2* h2 = reinterpret_cast<const float2*>(hs);
    float2 acc = h2[(size_t)gw * 32 + lane];
    int e = pbase[0], end = pbase[1];
    for (; e + 3 < end; e += 4) {
        int s0 = csr[e], s1 = csr[e + 1], s2 = csr[e + 2], s3 = csr[e + 3];
        float2 v0 = h2[(size_t)s0 * 32 + lane];
        float2 v1 = h2[(size_t)s1 * 32 + lane];
        float2 v2 = h2[(size_t)s2 * 32 + lane];
        float2 v3 = h2[(size_t)s3 * 32 + lane];
        acc.x += (v0.x + v1.x) + (v2.x + v3.x);
        acc.y += (v0.y + v1.y) + (v2.y + v3.y);
    }
    for (; e < end; e++) {
        int s0 = csr[e];
        float2 v0 = h2[(size_t)s0 * 32 + lane];
        acc.x += v0.x; acc.y += v0.y;
    }
    float dv = g_dinv[gw];
    float2 bb = reinterpret_cast<const float2*>(b)[lane];
    float2 o;
    o.x = fmaxf(fmaf(acc.x, dv, bb.x), 0.f);
    o.y = fmaxf(fmaf(acc.y, dv, bb.y), 0.f);
    reinterpret_cast<float2*>(out)[(size_t)gw * 32 + lane] = o;
}

// ---------------- K=64 GEMM via bf16-split mma: C = (A@W2)*dinv ------------
// u32 offsets in dynamic smem
#define G_AHI 0
#define G_ALO 4608
#define G_BHI 9216
#define G_BLO 11520
#define G_TOT 13824   // u32 -> 55296 bytes

__global__ __launch_bounds__(512) void k_gemm64b(
    const float* __restrict__ A, const float* __restrict__ W2,
    float* __restrict__ C)
{
    extern __shared__ uint32_t sg[];
    int tid = threadIdx.x, lane = tid & 31, w = tid >> 5;
    int grp = lane >> 2, tig = lane & 3;
    int wm = w >> 3, wn = w & 7;
    int row0 = blockIdx.x * 128;

    // B: [64 cols][32 kpairs + 4 pad]; element (col j, kpair kp) = W2[2kp..][j]
    for (int i = tid; i < 64 * 32; i += 512) {
        int j = i >> 5, kp = i & 31;
        float e0 = W2[(2 * kp) * 64 + j];
        float e1 = W2[(2 * kp + 1) * 64 + j];
        uint32_t hi, lo; split2(e0, e1, hi, lo);
        sg[G_BHI + j * 36 + kp] = hi;
        sg[G_BLO + j * 36 + kp] = lo;
    }
    // A rows (exact: T*N divisible by 128)
#pragma unroll
    for (int u = 0; u < 4; u++) {
        int ii = tid + u * 512;
        int r = ii >> 4, f4 = ii & 15;
        float4 v = *reinterpret_cast<const float4*>(A + (size_t)(row0 + r) * 64 + f4 * 4);
        uint32_t h0, l0, h1, l1;
        split2(v.x, v.y, h0, l0);
        split2(v.z, v.w, h1, l1);
        int bix = r * 36 + f4 * 2;
        sg[G_AHI + bix] = h0; sg[G_AHI + bix + 1] = h1;
        sg[G_ALO + bix] = l0; sg[G_ALO + bix + 1] = l1;
    }
    __syncthreads();

    float acc[4][4] = {};
#pragma unroll
    for (int cs = 0; cs < 4; cs++) {
        int kb = cs * 8;
        int pb = (wn * 8 + grp) * 36 + kb;
        uint32_t b0h = sg[G_BHI + pb + tig],  b1h = sg[G_BHI + pb + tig + 4];
        uint32_t b0l = sg[G_BLO + pb + tig],  b1l = sg[G_BLO + pb + tig + 4];
#pragma unroll
        for (int mi = 0; mi < 4; mi++) {
            int rb = wm * 64 + mi * 16;
            uint32_t Ah[4], Al[4];
            Ah[0] = sg[G_AHI + (rb + grp) * 36 + kb + tig];
            Ah[1] = sg[G_AHI + (rb + grp + 8) * 36 + kb + tig];
            Ah[2] = sg[G_AHI + (rb + grp) * 36 + kb + tig + 4];
            Ah[3] = sg[G_AHI + (rb + grp + 8) * 36 + kb + tig + 4];
            Al[0] = sg[G_ALO + (rb + grp) * 36 + kb + tig];
            Al[1] = sg[G_ALO + (rb + grp + 8) * 36 + kb + tig];
            Al[2] = sg[G_ALO + (rb + grp) * 36 + kb + tig + 4];
            Al[3] = sg[G_ALO + (rb + grp + 8) * 36 + kb + tig + 4];
            mma_bf16(acc[mi], Ah, b0h, b1h);
            mma_bf16(acc[mi], Ah, b0l, b1l);
            mma_bf16(acc[mi], Al, b0h, b1h);
        }
    }
#pragma unroll
    for (int mi = 0; mi < 4; mi++) {
#pragma unroll
        for (int rh = 0; rh < 2; rh++) {
            int row = row0 + wm * 64 + mi * 16 + grp + rh * 8;
            float dv = g_dinv[row];
            float2 o = make_float2(acc[mi][rh * 2] * dv, acc[mi][rh * 2 + 1] * dv);
            *reinterpret_cast<float2*>(C + (size_t)row * 64 + wn * 8 + tig * 2) = o;
        }
    }
}

// ============== fused LSTM over all T + head, bf16-split mma ===============
// u32 offsets in dynamic smem
#define L_XHI  0          // 128 x 36
#define L_XLO  4608
#define L_HHI  9216
#define L_HLO  13824
#define L_BHI  18432      // 256 x 68
#define L_BLO  35840
#define L_BIAS 53248      // 256 floats
#define L_LOG  53504      // 128 floats
#define L_TOT  53632      // u32 -> 214528 bytes

__global__ __launch_bounds__(512, 1) void k_lstm_bf16(
    const float* __restrict__ seq,
    const float* __restrict__ w_ih, const float* __restrict__ w_hh,
    const float* __restrict__ b_ih, const float* __restrict__ b_hh,
    const float* __restrict__ head_w, const float* __restrict__ head_b,
    float* __restrict__ out)
{
    extern __shared__ uint32_t sm_u[];
    float* sBias = reinterpret_cast<float*>(sm_u + L_BIAS);
    float* sLog  = reinterpret_cast<float*>(sm_u + L_LOG);

    int tid = threadIdx.x, lane = tid & 31, w = tid >> 5;
    int grp = lane >> 2, tig = lane & 3;
    int wm = w >> 3, wn = w & 7;
    int row0 = blockIdx.x * TILE_M;
    int j0 = (wn << 3) + tig, j1 = j0 + 4;

    // ---- B: permuted gate columns, split bf16, [256 cols][64 kpairs+4] ----
    // physical col p: gate = (q&1)*2 + (e&1); j = wnp*8 + (q>>1)*4 + (e>>1)
    for (int i = tid; i < 256 * 64; i += 512) {
        int p = i >> 6, kp = i & 63;
        int wnp = p >> 5, rem = p & 31, q = rem >> 3, e = rem & 7;
        int gate = ((q & 1) << 1) | (e & 1);
        int L = (gate << 6) + (wnp << 3) + ((q >> 1) << 2) + (e >> 1);
        int k = kp * 2;
        float2 v = (k < 64)
            ? *reinterpret_cast<const float2*>(w_ih + (size_t)L * 64 + k)
            : *reinterpret_cast<const float2*>(w_hh + (size_t)L * 64 + (k - 64));
        uint32_t hi, lo; split2(v.x, v.y, hi, lo);
        sm_u[L_BHI + p * 68 + kp] = hi;
        sm_u[L_BLO + p * 68 + kp] = lo;
    }
    // zero sH (hi + lo contiguous)
    for (int i = tid; i < 9216; i += 512) sm_u[L_HHI + i] = 0u;
    if (tid < 256) sBias[tid] = b_ih[tid] + b_hh[tid];
    if (tid < 128) sLog[tid] = 0.f;
    // load x(0)
    {
        const float* st = seq;
#pragma unroll
        for (int u = 0; u < 4; u++) {
            int ii = tid + u * 512;
            int r = ii >> 4, f4 = ii & 15;
            int row = row0 + r;
            float4 v = make_float4(0.f, 0.f, 0.f, 0.f);
            if (row < NN) v = *reinterpret_cast<const float4*>(st + (size_t)row * HH + f4 * 4);
            uint32_t h0, l0, h1, l1;
            split2(v.x, v.y, h0, l0);
            split2(v.z, v.w, h1, l1);
            int bix = r * 36 + f4 * 2;
            sm_u[L_XHI + bix] = h0; sm_u[L_XHI + bix + 1] = h1;
            sm_u[L_XLO + bix] = l0; sm_u[L_XLO + bix + 1] = l1;
        }
    }
    float hw0 = head_w[j0], hw1 = head_w[j1];
    float creg[4][2][2];
#pragma unroll
    for (int a = 0; a < 4; a++)
#pragma unroll
        for (int b = 0; b < 2; b++) { creg[a][b][0] = 0.f; creg[a][b][1] = 0.f; }
    __syncthreads();

    for (int t = 0; t < TT; t++) {
        float acc[4][4][4] = {};
#pragma unroll 1
        for (int cs = 0; cs < 8; cs++) {
            const uint32_t* Ahi;
            const uint32_t* Alo;
            int kb;
            if (cs < 4) { Ahi = sm_u + L_XHI; Alo = sm_u + L_XLO; kb = cs * 8; }
            else        { Ahi = sm_u + L_HHI; Alo = sm_u + L_HLO; kb = (cs - 4) * 8; }
            int kb2 = cs * 8;
            uint32_t Bh[4][2], Bl[4][2];
#pragma unroll
            for (int q = 0; q < 4; q++) {
                int pb = ((wn << 5) + (q << 3) + grp) * 68 + kb2;
                Bh[q][0] = sm_u[L_BHI + pb + tig];
                Bh[q][1] = sm_u[L_BHI + pb + tig + 4];
                Bl[q][0] = sm_u[L_BLO + pb + tig];
                Bl[q][1] = sm_u[L_BLO + pb + tig + 4];
            }
#pragma unroll
            for (int mi = 0; mi < 4; mi++) {
                int rb = wm * 64 + mi * 16;
                uint32_t Ah[4], Al[4];
                Ah[0] = Ahi[(rb + grp) * 36 + kb + tig];
                Ah[1] = Ahi[(rb + grp + 8) * 36 + kb + tig];
                Ah[2] = Ahi[(rb + grp) * 36 + kb + tig + 4];
                Ah[3] = Ahi[(rb + grp + 8) * 36 + kb + tig + 4];
                Al[0] = Alo[(rb + grp) * 36 + kb + tig];
                Al[1] = Alo[(rb + grp + 8) * 36 + kb + tig];
                Al[2] = Alo[(rb + grp) * 36 + kb + tig + 4];
                Al[3] = Alo[(rb + grp + 8) * 36 + kb + tig + 4];
#pragma unroll
                for (int q = 0; q < 4; q++) {
                    mma_bf16(acc[mi][q], Ah, Bh[q][0], Bh[q][1]);
                    mma_bf16(acc[mi][q], Ah, Bl[q][0], Bl[q][1]);
                    mma_bf16(acc[mi][q], Al, Bh[q][0], Bh[q][1]);
                }
            }
        }
        __syncthreads();   // all mma A/B reads done before sH/sX rewrite

        // ---- epilogue: gates -> c,h (c stays in registers) -----------------
        float bi0 = sBias[j0], bf0_ = sBias[64 + j0], bg0 = sBias[128 + j0], bo0 = sBias[192 + j0];
        float bi1 = sBias[j1], bf1_ = sBias[64 + j1], bg1 = sBias[128 + j1], bo1 = sBias[192 + j1];
#pragma unroll
        for (int mi = 0; mi < 4; mi++) {
#pragma unroll
            for (int rh = 0; rh < 2; rh++) {
                int r = wm * 64 + mi * 16 + grp + rh * 8;
                int ci = rh * 2;
                float gi0 = acc[mi][0][ci] + bi0, gf0 = acc[mi][0][ci + 1] + bf0_;
                float gg0 = acc[mi][1][ci] + bg0, go0 = acc[mi][1][ci + 1] + bo0;
                float gi1 = acc[mi][2][ci] + bi1, gf1 = acc[mi][2][ci + 1] + bf1_;
                float gg1 = acc[mi][3][ci] + bg1, go1 = acc[mi][3][ci + 1] + bo1;
                float c0 = creg[mi][rh][0], c1 = creg[mi][rh][1];
                c0 = sigf(gf0) * c0 + sigf(gi0) * tanhf_fast(gg0);
                c1 = sigf(gf1) * c1 + sigf(gi1) * tanhf_fast(gg1);
                creg[mi][rh][0] = c0; creg[mi][rh][1] = c1;
                float h0 = sigf(go0) * tanhf_fast(c0);
                float h1 = sigf(go1) * tanhf_fast(c1);
                if (t < TT - 1) {
                    int base0 = r * 36 + (j0 >> 1);
                    int sl = j0 & 1;
                    __nv_bfloat16 b0 = __float2bfloat16(h0);
                    reinterpret_cast<__nv_bfloat16*>(&sm_u[L_HHI + base0])[sl] = b0;
                    reinterpret_cast<__nv_bfloat16*>(&sm_u[L_HLO + base0])[sl] =
                        __float2bfloat16(h0 - __bfloat162float(b0));
                    __nv_bfloat16 b1 = __float2bfloat16(h1);
                    reinterpret_cast<__nv_bfloat16*>(&sm_u[L_HHI + base0 + 2])[sl] = b1;
                    reinterpret_cast<__nv_bfloat16*>(&sm_u[L_HLO + base0 + 2])[sl] =
                        __float2bfloat16(h1 - __bfloat162float(b1));
                } else {
                    float v = h0 * hw0 + h1 * hw1;
                    v += __shfl_xor_sync(0xffffffffu, v, 1);
                    v += __shfl_xor_sync(0xffffffffu, v, 2);
                    if (tig == 0) atomicAdd(&sLog[r], v);
                }
            }
        }

        // ---- load x(t+1) ---------------------------------------------------
        if (t < TT - 1) {
            const float* st = seq + (size_t)(t + 1) * NN * HH;
#pragma unroll
            for (int u = 0; u < 4; u++) {
                int ii = tid + u * 512;
                int r = ii >> 4, f4 = ii & 15;
                int row = row0 + r;
                float4 v = make_float4(0.f, 0.f, 0.f, 0.f);
                if (row < NN) v = *reinterpret_cast<const float4*>(st + (size_t)row * HH + f4 * 4);
                uint32_t h0, l0, h1, l1;
                split2(v.x, v.y, h0, l0);
                split2(v.z, v.w, h1, l1);
                int bix = r * 36 + f4 * 2;
                sm_u[L_XHI + bix] = h0; sm_u[L_XHI + bix + 1] = h1;
                sm_u[L_XLO + bix] = l0; sm_u[L_XLO + bix + 1] = l1;
            }
        }
        __syncthreads();
    }

    if (tid < 128) {
        int row = row0 + tid;
        if (row < NN) out[row] = sLog[tid] + head_b[0];
    }
}

// ---------------- host launch ----------------------------------------------
extern "C" void kernel_launch(void* const* d_in, const int* in_sizes, int n_in,
                              void* d_out, int out_size) {
    const float* xs  = (const float*)d_in[0];
    const int*   ei  = (const int*)  d_in[1];
    const float* W1  = (const float*)d_in[2];
    const float* b1  = (const float*)d_in[3];
    const float* W2  = (const float*)d_in[4];
    const float* b2  = (const float*)d_in[5];
    const float* wih = (const float*)d_in[6];
    const float* whh = (const float*)d_in[7];
    const float* bih = (const float*)d_in[8];
    const float* bhh = (const float*)d_in[9];
    const float* hw  = (const float*)d_in[10];
    const float* hb  = (const float*)d_in[11];
    float* out = (float*)d_out;

    float *p_hs, *p_act;
    cudaGetSymbolAddress((void**)&p_hs,  g_hs);
    cudaGetSymbolAddress((void**)&p_act, g_act);

    cudaFuncSetAttribute(k_lstm_bf16,
                         cudaFuncAttributeMaxDynamicSharedMemorySize, L_TOT * 4);
    cudaFuncSetAttribute(k_gemm64b,
                         cudaFuncAttributeMaxDynamicSharedMemorySize, G_TOT * 4);

    k_init<<<(TT * NN + 255) / 256, 256>>>();
    k_hist_all<<<(TT * EE + 255) / 256, 256>>>(ei);
    k_scan_all<<<TT, 1024>>>();
    k_fill_all<<<(TT * EE + 255) / 256, 256>>>(ei);

    k_gemm1<<<(TT * NN + 127) / 128, 128>>>(xs, W1);
    k_agg<<<((size_t)TT * NN * 32 + 511) / 512, 512>>>(p_hs, p_act, b1);
    k_gemm64b<<<(TT * NN) / 128, 512, G_TOT * 4>>>(p_act, W2, p_hs);
    k_agg<<<((size_t)TT * NN * 32 + 511) / 512, 512>>>(p_hs, p_act, b2);

    k_lstm_bf16<<<NBLK, 512, L_TOT * 4>>>(p_act, wih, whh, bih, bhh, hw, hb, out);
}